// round 10
// baseline (speedup 1.0000x reference)
#include <cuda_runtime.h>

// Problem constants
#define HWT  262144            // 64*64*64
#define NCTA 16384             // 65536 windows / 4 per CTA
// msg scratch, blocked layout [cta][96][32]  (201 MB)
__device__ float g_msg[(long)NCTA * 96 * 32];

// Packed dual-FMA (Blackwell f32x2). 2 FMAs per instruction.
__device__ __forceinline__ float2 ffma2(float2 a, float2 b, float2 c) {
    float2 d;
    asm("fma.rn.f32x2 %0, %1, %2, %3;"
        : "=l"(reinterpret_cast<unsigned long long&>(d))
        : "l"(reinterpret_cast<unsigned long long&>(a)),
          "l"(reinterpret_cast<unsigned long long&>(b)),
          "l"(reinterpret_cast<unsigned long long&>(c)));
    return d;
}

// Tile GEMM: 32 tokens x 96 cols, A in SMEM duplicated layout [k][2*tok] (stride ASTR),
// W row-major [K][WSTR] in global (pointer pre-offset by this thread's column base).
// Thread (ty,tx): tokens {ty, ty+8, ty+16, ty+24}, col pairs {2tx+32i, 2tx+32i+1}, i<3.
template <int K, int WSTR, int ASTR>
__device__ __forceinline__ void gemm_tile(const float* __restrict__ A,
                                          const float* __restrict__ W,
                                          float2 acc[4][3], int ty)
{
    #pragma unroll
    for (int r = 0; r < 4; r++)
        #pragma unroll
        for (int i = 0; i < 3; i++) acc[r][i] = make_float2(0.f, 0.f);

    #pragma unroll 8
    for (int k = 0; k < K; k++) {
        float2 a0 = *(const float2*)(A + k * ASTR + 2 * ty);
        float2 a1 = *(const float2*)(A + k * ASTR + 2 * ty + 16);
        float2 a2 = *(const float2*)(A + k * ASTR + 2 * ty + 32);
        float2 a3 = *(const float2*)(A + k * ASTR + 2 * ty + 48);
        #pragma unroll
        for (int i = 0; i < 3; i++) {
            float2 w = *(const float2*)(W + k * WSTR + 32 * i);
            acc[0][i] = ffma2(a0, w, acc[0][i]);
            acc[1][i] = ffma2(a1, w, acc[1][i]);
            acc[2][i] = ffma2(a2, w, acc[2][i]);
            acc[3][i] = ffma2(a3, w, acc[3][i]);
        }
    }
}

// ---------------------------------------------------------------------------
// Kernel 1: windowed MHSA. CTA = 4 t-consecutive 2x2x2 windows (32 tokens).
// SMEM: XsD [96][64] dup-token A-operand; QKVs [32][288] (reused as OutT[96][33]).
// ---------------------------------------------------------------------------
__global__ void __launch_bounds__(128) k_attn(
    const float* __restrict__ x,
    const float* __restrict__ qkv_w, const float* __restrict__ qkv_b,
    const float* __restrict__ merge_w, const float* __restrict__ merge_b)
{
    extern __shared__ float smem[];
    float* XsD  = smem;          // 96*64 = 6144 floats
    float* QKVs = smem + 6144;   // 32*288 = 9216 floats

    const int tid = threadIdx.x;
    const int cid = blockIdx.x;
    const int tw0 = (cid & 7) * 4;
    int rest = cid >> 3;
    const int ww = rest & 31; rest >>= 5;
    const int hw = rest & 31;
    const int b  = rest >> 5;

    // ---- gather X: warp wp handles channels c = wp, wp+4, ... ----
    const int wp = tid >> 5, lane = tid & 31;
    const int seg = lane >> 3, toff = lane & 7;
    const int jh = seg >> 1, jw = seg & 1;
    const int g_tok = (toff >> 1) * 8 + jh * 4 + jw * 2 + (toff & 1);
    const long spat = (long)(hw * 2 + jh) * 4096 + (ww * 2 + jw) * 64 + (tw0 * 2 + toff);
    const float* xb = x + (long)b * 96 * HWT + spat;
    #pragma unroll
    for (int c = wp; c < 96; c += 4) {
        float v = __ldg(xb + (long)c * HWT);
        XsD[c * 64 + 2 * g_tok]     = v;
        XsD[c * 64 + 2 * g_tok + 1] = v;
    }
    __syncthreads();

    const int ty = tid >> 4, tx = tid & 15;

    // ---- QKV GEMM: [32x96] @ [96x288] in 3 passes of 96 cols ----
    for (int pass = 0; pass < 3; pass++) {
        const int cb = pass * 96 + 2 * tx;
        float2 acc[4][3];
        gemm_tile<96, 288, 64>(XsD, qkv_w + cb, acc, ty);
        #pragma unroll
        for (int i = 0; i < 3; i++) {
            float2 bia = *(const float2*)(qkv_b + cb + 32 * i);
            #pragma unroll
            for (int r = 0; r < 4; r++) {
                float2 v = acc[r][i];
                v.x += bia.x; v.y += bia.y;
                *(float2*)(QKVs + (ty + 8 * r) * 288 + cb + 32 * i) = v;
            }
        }
    }
    __syncthreads();

    // ---- attention: group = (window, head); 4 threads/group, 2 rows/thread ----
    {
        const int g = tid >> 2;
        const int wl = g >> 3, h = g & 7;
        const int sub = tid & 3;
        const float scale = rsqrtf(12.0f);
        #pragma unroll
        for (int rr = 0; rr < 2; rr++) {
            const int i = sub + 4 * rr;
            const int ti = wl * 8 + i;
            float q[12];
            #pragma unroll
            for (int d = 0; d < 12; d++) q[d] = QKVs[ti * 288 + h * 12 + d] * scale;
            float s[8];
            #pragma unroll
            for (int j = 0; j < 8; j++) {
                const float* kj = QKVs + (wl * 8 + j) * 288 + 96 + h * 12;
                float a = 0.f;
                #pragma unroll
                for (int d = 0; d < 12; d++) a += q[d] * kj[d];
                s[j] = a;
            }
            float m = s[0];
            #pragma unroll
            for (int j = 1; j < 8; j++) m = fmaxf(m, s[j]);
            float sum = 0.f;
            #pragma unroll
            for (int j = 0; j < 8; j++) { s[j] = __expf(s[j] - m); sum += s[j]; }
            const float inv = 1.0f / sum;
            float o[12];
            #pragma unroll
            for (int d = 0; d < 12; d++) o[d] = 0.f;
            #pragma unroll
            for (int j = 0; j < 8; j++) {
                const float p = s[j] * inv;
                const float* vj = QKVs + (wl * 8 + j) * 288 + 192 + h * 12;
                #pragma unroll
                for (int d = 0; d < 12; d++) o[d] += p * vj[d];
            }
            // write attention output back into XsD (dup layout) for merge GEMM
            #pragma unroll
            for (int d = 0; d < 12; d++) {
                XsD[(h * 12 + d) * 64 + 2 * ti]     = o[d];
                XsD[(h * 12 + d) * 64 + 2 * ti + 1] = o[d];
            }
        }
    }
    __syncthreads();

    // ---- merge GEMM: [32x96] @ [96x96] + bias -> OutT (reusing QKVs region) ----
    {
        const int cb = 2 * tx;
        float2 acc[4][3];
        gemm_tile<96, 96, 64>(XsD, merge_w + cb, acc, ty);
        float* OutT = QKVs;  // [96][33]
        #pragma unroll
        for (int i = 0; i < 3; i++) {
            float2 bia = *(const float2*)(merge_b + cb + 32 * i);
            #pragma unroll
            for (int r = 0; r < 4; r++) {
                const int tok = ty + 8 * r;
                OutT[(cb + 32 * i)     * 33 + tok] = acc[r][i].x + bia.x;
                OutT[(cb + 32 * i + 1) * 33 + tok] = acc[r][i].y + bia.y;
            }
        }
    }
    __syncthreads();

    // ---- write msg in blocked layout (fully coalesced) ----
    {
        float* dst = g_msg + (long)cid * 3072;
        const float* OutT = QKVs;
        #pragma unroll
        for (int idx = tid; idx < 3072; idx += 128)
            dst[idx] = OutT[(idx >> 5) * 33 + (idx & 31)];
    }
}

// ---------------------------------------------------------------------------
// Kernel 2: MLP. CTA = same 4 windows (32 tokens).
// SMEM: InD [192][64] dup ([x | msg]); HmD [96][66] dup; OutT reuses InD.
// ---------------------------------------------------------------------------
__global__ void __launch_bounds__(128) k_mlp(
    const float* __restrict__ x,
    const float* __restrict__ w1, const float* __restrict__ b1,
    const float* __restrict__ w2, const float* __restrict__ b2,
    float* __restrict__ out)
{
    extern __shared__ float smem[];
    float* InD = smem;            // 192*64 = 12288 floats
    float* HmD = smem + 12288;    // 96*66  = 6336 floats

    const int tid = threadIdx.x;
    const int cid = blockIdx.x;
    const int tw0 = (cid & 7) * 4;
    int rest = cid >> 3;
    const int ww = rest & 31; rest >>= 5;
    const int hw = rest & 31;
    const int b  = rest >> 5;

    const int wp = tid >> 5, lane = tid & 31;
    const int seg = lane >> 3, toff = lane & 7;
    const int jh = seg >> 1, jw = seg & 1;
    const int g_tok = (toff >> 1) * 8 + jh * 4 + jw * 2 + (toff & 1);
    const long spat = (long)(hw * 2 + jh) * 4096 + (ww * 2 + jw) * 64 + (tw0 * 2 + toff);

    // ---- gather x into rows 0..95 ----
    const float* xb = x + (long)b * 96 * HWT + spat;
    #pragma unroll
    for (int c = wp; c < 96; c += 4) {
        float v = __ldg(xb + (long)c * HWT);
        InD[c * 64 + 2 * g_tok]     = v;
        InD[c * 64 + 2 * g_tok + 1] = v;
    }
    // ---- load msg (blocked, coalesced) into rows 96..191 ----
    {
        const float* msrc = g_msg + (long)cid * 3072;
        #pragma unroll
        for (int idx = tid; idx < 3072; idx += 128) {
            const int c = idx >> 5, tok = idx & 31;
            float v = msrc[idx];
            InD[(96 + c) * 64 + 2 * tok]     = v;
            InD[(96 + c) * 64 + 2 * tok + 1] = v;
        }
    }
    __syncthreads();

    const int ty = tid >> 4, tx = tid & 15;
    const int cb = 2 * tx;

    // ---- MLP1: [32x192] @ [192x96] + b1, exact GELU -> HmD dup ----
    {
        float2 acc[4][3];
        gemm_tile<192, 96, 64>(InD, w1 + cb, acc, ty);
        #pragma unroll
        for (int i = 0; i < 3; i++) {
            float2 bia = *(const float2*)(b1 + cb + 32 * i);
            #pragma unroll
            for (int r = 0; r < 4; r++) {
                const int tok = ty + 8 * r;
                float hx = acc[r][i].x + bia.x;
                float hy = acc[r][i].y + bia.y;
                hx = hx * normcdff(hx);      // exact GELU
                hy = hy * normcdff(hy);
                const int c0 = cb + 32 * i;
                HmD[c0 * 66 + 2 * tok]           = hx;
                HmD[c0 * 66 + 2 * tok + 1]       = hx;
                HmD[(c0 + 1) * 66 + 2 * tok]     = hy;
                HmD[(c0 + 1) * 66 + 2 * tok + 1] = hy;
            }
        }
    }
    __syncthreads();

    // ---- MLP2: [32x96] @ [96x96] + b2 -> OutT (reusing InD region) ----
    {
        float2 acc[4][3];
        gemm_tile<96, 96, 66>(HmD, w2 + cb, acc, ty);
        float* OutT = InD;  // [96][33]
        #pragma unroll
        for (int i = 0; i < 3; i++) {
            float2 bia = *(const float2*)(b2 + cb + 32 * i);
            #pragma unroll
            for (int r = 0; r < 4; r++) {
                const int tok = ty + 8 * r;
                OutT[(cb + 32 * i)     * 33 + tok] = acc[r][i].x + bia.x;
                OutT[(cb + 32 * i + 1) * 33 + tok] = acc[r][i].y + bia.y;
            }
        }
    }
    __syncthreads();

    // ---- scatter to channel-major output (inverse gather: full 32B sectors) ----
    {
        const float* OutT = InD;
        float* ob = out + (long)b * 96 * HWT + spat;
        #pragma unroll
        for (int c = wp; c < 96; c += 4)
            ob[(long)c * HWT] = OutT[c * 33 + g_tok];
    }
}

// ---------------------------------------------------------------------------
extern "C" void kernel_launch(void* const* d_in, const int* in_sizes, int n_in,
                              void* d_out, int out_size)
{
    const float* x       = (const float*)d_in[0];
    const float* qkv_w   = (const float*)d_in[1];
    const float* qkv_b   = (const float*)d_in[2];
    const float* merge_w = (const float*)d_in[3];
    const float* merge_b = (const float*)d_in[4];
    const float* w1      = (const float*)d_in[5];
    const float* b1      = (const float*)d_in[6];
    const float* w2      = (const float*)d_in[7];
    const float* b2      = (const float*)d_in[8];
    float* out = (float*)d_out;

    const int smem1 = (96 * 64 + 32 * 288) * 4;   // 61440 B
    const int smem2 = (192 * 64 + 96 * 66) * 4;   // 74496 B
    cudaFuncSetAttribute((const void*)k_attn, cudaFuncAttributeMaxDynamicSharedMemorySize, smem1);
    cudaFuncSetAttribute((const void*)k_mlp,  cudaFuncAttributeMaxDynamicSharedMemorySize, smem2);

    k_attn<<<NCTA, 128, smem1>>>(x, qkv_w, qkv_b, merge_w, merge_b);
    k_mlp <<<NCTA, 128, smem2>>>(x, w1, b1, w2, b2, out);
}

// round 11
// speedup vs baseline: 1.0433x; 1.0433x over previous
#include <cuda_runtime.h>

// Problem constants
#define HWT  262144            // 64*64*64
#define NCTA 16384             // 65536 windows / 4 per CTA
// msg scratch, blocked layout [cta][96][32]  (201 MB)
__device__ float g_msg[(long)NCTA * 96 * 32];

// Packed dual-FMA (Blackwell f32x2). 2 FMAs per instruction.
__device__ __forceinline__ float2 ffma2(float2 a, float2 b, float2 c) {
    float2 d;
    asm("fma.rn.f32x2 %0, %1, %2, %3;"
        : "=l"(reinterpret_cast<unsigned long long&>(d))
        : "l"(reinterpret_cast<unsigned long long&>(a)),
          "l"(reinterpret_cast<unsigned long long&>(b)),
          "l"(reinterpret_cast<unsigned long long&>(c)));
    return d;
}

// Tile GEMM: 32 tokens x 96 cols, A in SMEM duplicated layout [k][2*tok] (stride ASTR),
// W row-major [K][WSTR] in global (pointer pre-offset by this thread's column base).
// Thread (ty,tx): tokens {ty, ty+8, ty+16, ty+24}, col pairs {2tx+32i, 2tx+32i+1}, i<3.
template <int K, int WSTR, int ASTR>
__device__ __forceinline__ void gemm_tile(const float* __restrict__ A,
                                          const float* __restrict__ W,
                                          float2 acc[4][3], int ty)
{
    #pragma unroll
    for (int r = 0; r < 4; r++)
        #pragma unroll
        for (int i = 0; i < 3; i++) acc[r][i] = make_float2(0.f, 0.f);

    #pragma unroll 8
    for (int k = 0; k < K; k++) {
        float2 a0 = *(const float2*)(A + k * ASTR + 2 * ty);
        float2 a1 = *(const float2*)(A + k * ASTR + 2 * ty + 16);
        float2 a2 = *(const float2*)(A + k * ASTR + 2 * ty + 32);
        float2 a3 = *(const float2*)(A + k * ASTR + 2 * ty + 48);
        #pragma unroll
        for (int i = 0; i < 3; i++) {
            float2 w = *(const float2*)(W + k * WSTR + 32 * i);
            acc[0][i] = ffma2(a0, w, acc[0][i]);
            acc[1][i] = ffma2(a1, w, acc[1][i]);
            acc[2][i] = ffma2(a2, w, acc[2][i]);
            acc[3][i] = ffma2(a3, w, acc[3][i]);
        }
    }
}

// ---------------------------------------------------------------------------
// Kernel 1: windowed MHSA. CTA = 4 t-consecutive 2x2x2 windows (32 tokens).
// SMEM: XsD [96][64] dup-token A-operand; QKVs [32][288] (reused as OutT[96][33]).
// ---------------------------------------------------------------------------
__global__ void __launch_bounds__(128) k_attn(
    const float* __restrict__ x,
    const float* __restrict__ qkv_w, const float* __restrict__ qkv_b,
    const float* __restrict__ merge_w, const float* __restrict__ merge_b)
{
    extern __shared__ float smem[];
    float* XsD  = smem;          // 96*64 = 6144 floats
    float* QKVs = smem + 6144;   // 32*288 = 9216 floats

    const int tid = threadIdx.x;
    const int cid = blockIdx.x;
    const int tw0 = (cid & 7) * 4;
    int rest = cid >> 3;
    const int ww = rest & 31; rest >>= 5;
    const int hw = rest & 31;
    const int b  = rest >> 5;

    // ---- gather X: warp wp handles channels c = wp, wp+4, ... ----
    const int wp = tid >> 5, lane = tid & 31;
    const int seg = lane >> 3, toff = lane & 7;
    const int jh = seg >> 1, jw = seg & 1;
    const int g_tok = (toff >> 1) * 8 + jh * 4 + jw * 2 + (toff & 1);
    const long spat = (long)(hw * 2 + jh) * 4096 + (ww * 2 + jw) * 64 + (tw0 * 2 + toff);
    const float* xb = x + (long)b * 96 * HWT + spat;
    #pragma unroll
    for (int c = wp; c < 96; c += 4) {
        float v = __ldg(xb + (long)c * HWT);
        XsD[c * 64 + 2 * g_tok]     = v;
        XsD[c * 64 + 2 * g_tok + 1] = v;
    }
    __syncthreads();

    const int ty = tid >> 4, tx = tid & 15;

    // ---- QKV GEMM: [32x96] @ [96x288] in 3 passes of 96 cols ----
    for (int pass = 0; pass < 3; pass++) {
        const int cb = pass * 96 + 2 * tx;
        float2 acc[4][3];
        gemm_tile<96, 288, 64>(XsD, qkv_w + cb, acc, ty);
        #pragma unroll
        for (int i = 0; i < 3; i++) {
            float2 bia = *(const float2*)(qkv_b + cb + 32 * i);
            #pragma unroll
            for (int r = 0; r < 4; r++) {
                float2 v = acc[r][i];
                v.x += bia.x; v.y += bia.y;
                *(float2*)(QKVs + (ty + 8 * r) * 288 + cb + 32 * i) = v;
            }
        }
    }
    __syncthreads();

    // ---- attention: group = (window, head); 4 threads/group, 2 rows/thread ----
    {
        const int g = tid >> 2;
        const int wl = g >> 3, h = g & 7;
        const int sub = tid & 3;
        const float scale = rsqrtf(12.0f);
        #pragma unroll
        for (int rr = 0; rr < 2; rr++) {
            const int i = sub + 4 * rr;
            const int ti = wl * 8 + i;
            float q[12];
            #pragma unroll
            for (int d = 0; d < 12; d++) q[d] = QKVs[ti * 288 + h * 12 + d] * scale;
            float s[8];
            #pragma unroll
            for (int j = 0; j < 8; j++) {
                const float* kj = QKVs + (wl * 8 + j) * 288 + 96 + h * 12;
                float a = 0.f;
                #pragma unroll
                for (int d = 0; d < 12; d++) a += q[d] * kj[d];
                s[j] = a;
            }
            float m = s[0];
            #pragma unroll
            for (int j = 1; j < 8; j++) m = fmaxf(m, s[j]);
            float sum = 0.f;
            #pragma unroll
            for (int j = 0; j < 8; j++) { s[j] = __expf(s[j] - m); sum += s[j]; }
            const float inv = 1.0f / sum;
            float o[12];
            #pragma unroll
            for (int d = 0; d < 12; d++) o[d] = 0.f;
            #pragma unroll
            for (int j = 0; j < 8; j++) {
                const float p = s[j] * inv;
                const float* vj = QKVs + (wl * 8 + j) * 288 + 192 + h * 12;
                #pragma unroll
                for (int d = 0; d < 12; d++) o[d] += p * vj[d];
            }
            // write attention output back into XsD (dup layout) for merge GEMM
            #pragma unroll
            for (int d = 0; d < 12; d++) {
                XsD[(h * 12 + d) * 64 + 2 * ti]     = o[d];
                XsD[(h * 12 + d) * 64 + 2 * ti + 1] = o[d];
            }
        }
    }
    __syncthreads();

    // ---- merge GEMM: [32x96] @ [96x96] + bias -> OutT (reusing QKVs region) ----
    {
        const int cb = 2 * tx;
        float2 acc[4][3];
        gemm_tile<96, 96, 64>(XsD, merge_w + cb, acc, ty);
        float* OutT = QKVs;  // [96][33]
        #pragma unroll
        for (int i = 0; i < 3; i++) {
            float2 bia = *(const float2*)(merge_b + cb + 32 * i);
            #pragma unroll
            for (int r = 0; r < 4; r++) {
                const int tok = ty + 8 * r;
                OutT[(cb + 32 * i)     * 33 + tok] = acc[r][i].x + bia.x;
                OutT[(cb + 32 * i + 1) * 33 + tok] = acc[r][i].y + bia.y;
            }
        }
    }
    __syncthreads();

    // ---- write msg in blocked layout (fully coalesced) ----
    {
        float* dst = g_msg + (long)cid * 3072;
        const float* OutT = QKVs;
        #pragma unroll
        for (int idx = tid; idx < 3072; idx += 128)
            dst[idx] = OutT[(idx >> 5) * 33 + (idx & 31)];
    }
}

// ---------------------------------------------------------------------------
// Kernel 2: MLP. CTA = same 4 windows (32 tokens).
// SMEM: InD [192][64] dup ([x | msg]); HmD [96][66] dup; OutT reuses InD.
// ---------------------------------------------------------------------------
__global__ void __launch_bounds__(128) k_mlp(
    const float* __restrict__ x,
    const float* __restrict__ w1, const float* __restrict__ b1,
    const float* __restrict__ w2, const float* __restrict__ b2,
    float* __restrict__ out)
{
    extern __shared__ float smem[];
    float* InD = smem;            // 192*64 = 12288 floats
    float* HmD = smem + 12288;    // 96*66  = 6336 floats

    const int tid = threadIdx.x;
    const int cid = blockIdx.x;
    const int tw0 = (cid & 7) * 4;
    int rest = cid >> 3;
    const int ww = rest & 31; rest >>= 5;
    const int hw = rest & 31;
    const int b  = rest >> 5;

    const int wp = tid >> 5, lane = tid & 31;
    const int seg = lane >> 3, toff = lane & 7;
    const int jh = seg >> 1, jw = seg & 1;
    const int g_tok = (toff >> 1) * 8 + jh * 4 + jw * 2 + (toff & 1);
    const long spat = (long)(hw * 2 + jh) * 4096 + (ww * 2 + jw) * 64 + (tw0 * 2 + toff);

    // ---- gather x into rows 0..95 ----
    const float* xb = x + (long)b * 96 * HWT + spat;
    #pragma unroll
    for (int c = wp; c < 96; c += 4) {
        float v = __ldg(xb + (long)c * HWT);
        InD[c * 64 + 2 * g_tok]     = v;
        InD[c * 64 + 2 * g_tok + 1] = v;
    }
    // ---- load msg (blocked, coalesced) into rows 96..191 ----
    {
        const float* msrc = g_msg + (long)cid * 3072;
        #pragma unroll
        for (int idx = tid; idx < 3072; idx += 128) {
            const int c = idx >> 5, tok = idx & 31;
            float v = msrc[idx];
            InD[(96 + c) * 64 + 2 * tok]     = v;
            InD[(96 + c) * 64 + 2 * tok + 1] = v;
        }
    }
    __syncthreads();

    const int ty = tid >> 4, tx = tid & 15;
    const int cb = 2 * tx;

    // ---- MLP1: [32x192] @ [192x96] + b1, exact GELU -> HmD dup ----
    {
        float2 acc[4][3];
        gemm_tile<192, 96, 64>(InD, w1 + cb, acc, ty);
        #pragma unroll
        for (int i = 0; i < 3; i++) {
            float2 bia = *(const float2*)(b1 + cb + 32 * i);
            #pragma unroll
            for (int r = 0; r < 4; r++) {
                const int tok = ty + 8 * r;
                float hx = acc[r][i].x + bia.x;
                float hy = acc[r][i].y + bia.y;
                hx = hx * normcdff(hx);      // exact GELU
                hy = hy * normcdff(hy);
                const int c0 = cb + 32 * i;
                HmD[c0 * 66 + 2 * tok]           = hx;
                HmD[c0 * 66 + 2 * tok + 1]       = hx;
                HmD[(c0 + 1) * 66 + 2 * tok]     = hy;
                HmD[(c0 + 1) * 66 + 2 * tok + 1] = hy;
            }
        }
    }
    __syncthreads();

    // ---- MLP2: [32x96] @ [96x96] + b2 -> OutT (reusing InD region) ----
    {
        float2 acc[4][3];
        gemm_tile<96, 96, 66>(HmD, w2 + cb, acc, ty);
        float* OutT = InD;  // [96][33]
        #pragma unroll
        for (int i = 0; i < 3; i++) {
            float2 bia = *(const float2*)(b2 + cb + 32 * i);
            #pragma unroll
            for (int r = 0; r < 4; r++) {
                const int tok = ty + 8 * r;
                OutT[(cb + 32 * i)     * 33 + tok] = acc[r][i].x + bia.x;
                OutT[(cb + 32 * i + 1) * 33 + tok] = acc[r][i].y + bia.y;
            }
        }
    }
    __syncthreads();

    // ---- scatter to channel-major output (inverse gather: full 32B sectors) ----
    {
        const float* OutT = InD;
        float* ob = out + (long)b * 96 * HWT + spat;
        #pragma unroll
        for (int c = wp; c < 96; c += 4)
            ob[(long)c * HWT] = OutT[c * 33 + g_tok];
    }
}

// ---------------------------------------------------------------------------
extern "C" void kernel_launch(void* const* d_in, const int* in_sizes, int n_in,
                              void* d_out, int out_size)
{
    const float* x       = (const float*)d_in[0];
    const float* qkv_w   = (const float*)d_in[1];
    const float* qkv_b   = (const float*)d_in[2];
    const float* merge_w = (const float*)d_in[3];
    const float* merge_b = (const float*)d_in[4];
    const float* w1      = (const float*)d_in[5];
    const float* b1      = (const float*)d_in[6];
    const float* w2      = (const float*)d_in[7];
    const float* b2      = (const float*)d_in[8];
    float* out = (float*)d_out;

    const int smem1 = (96 * 64 + 32 * 288) * 4;   // 61440 B
    const int smem2 = (192 * 64 + 96 * 66) * 4;   // 74496 B
    cudaFuncSetAttribute((const void*)k_attn, cudaFuncAttributeMaxDynamicSharedMemorySize, smem1);
    cudaFuncSetAttribute((const void*)k_mlp,  cudaFuncAttributeMaxDynamicSharedMemorySize, smem2);

    k_attn<<<NCTA, 128, smem1>>>(x, qkv_w, qkv_b, merge_w, merge_b);
    k_mlp <<<NCTA, 128, smem2>>>(x, w1, b1, w2, b2, out);
}